// round 10
// baseline (speedup 1.0000x reference)
#include <cuda_runtime.h>
#include <cuda_fp16.h>

// LODs = int(16*(256/16)^(L/7)) = 16,23,35,52,78,115,172,256
// entries: 256, 529, 1225, 2704, 6084, 13225, 29584, 65536
// LODs 0-5 in smem as scaled __half2 (24023*4B = 96.1KB -> 2 blocks/SM,
// 64 warps). LOD6 + LOD7 from global (L2-resident fp32).
//
// 8-point warp tile, chunk-per-lane: lane l = a*4+c handles chunk c of point
// base+a. No shuffles; one fully-coalesced STG.128 per lane.
//   chunk 0: x of LODs0-3   chunk 1: x of LODs4-7
//   chunk 2: y of LODs0-3   chunk 3: y of LODs4-7

#define SMEM_H2 24023
#define SMEM_BYTES (SMEM_H2 * 4)
#define SD (1.0f / 1024.0f)
#define SU 1024.0f
#define TPB 1024

__global__ void __launch_bounds__(TPB, 2)
dense_grid_occ8_kernel(const float2* __restrict__ pts,
                       const float2* __restrict__ cb0,
                       const float2* __restrict__ cb1,
                       const float2* __restrict__ cb2,
                       const float2* __restrict__ cb3,
                       const float2* __restrict__ cb4,
                       const float2* __restrict__ cb5,
                       const float2* __restrict__ cb6,
                       const float2* __restrict__ cb7,
                       float4* __restrict__ out,
                       int n)
{
    extern __shared__ __half2 sh[];

    // ---- Stage LODs 0-5 into smem as scaled half2 (coalesced) ----
    {
        const float2* __restrict__ srcs[6] = {cb0, cb1, cb2, cb3, cb4, cb5};
        const int cnt[6] = {256, 529, 1225, 2704, 6084, 13225};
        const int off[6] = {0, 256, 785, 2010, 4714, 10798};
#pragma unroll
        for (int L = 0; L < 6; ++L) {
            const float2* src = srcs[L];
            __half2* dst = sh + off[L];
            const int cn = cnt[L];
            for (int j = threadIdx.x; j < cn; j += TPB) {
                const float2 v = __ldg(&src[j]);
                dst[j] = __floats2half2_rn(v.x * SU, v.y * SU);
            }
        }
    }
    __syncthreads();

    const int l = threadIdx.x & 31;
    const int c = l & 3;
    const bool odd = (c & 1);        // odd chunk -> LODs 4-7
    const bool ycomp = (c & 2) != 0; // high chunk -> y component
    const int a = l >> 2;

    // Per-lane LOD-set constants (hoisted).
    const float sc0 = odd ? 77.0f : 15.0f;
    const float sc1 = odd ? 114.0f : 22.0f;
    const float sc2 = odd ? 171.0f : 34.0f;
    const float sc3 = odd ? 255.0f : 51.0f;
    const int r0 = odd ? 78 : 16;
    const int r1 = odd ? 115 : 23;
    const int r2 = odd ? 172 : 35;
    const int r3 = odd ? 256 : 52;
    const int o0 = odd ? 4714 : 0;     // LOD4 / LOD0
    const int o1 = odd ? 10798 : 256;  // LOD5 / LOD1
    const int o2 = 785;                // LOD2 (even path only)
    const int o3 = 2010;               // LOD3 (even path only)

    // Each warp owns 8 consecutive points per iteration (n % 8 == 0).
    const int warp_base0 = (blockIdx.x * TPB + (threadIdx.x & ~31)) >> 2;
    const int stride = (gridDim.x * TPB) >> 2;   // points per sweep

    for (int base = warp_base0; base < n; base += stride) {
        // 4-way-broadcast, read-once point load.
        const float2 p = __ldcs(&pts[base + a]);
        const float px = p.x, py = p.y;

        // trunc == floor for nonneg; same single fp32 multiply as reference
        const int i0 = (int)(px * sc0) + (int)(py * sc0) * r0;
        const int i1 = (int)(px * sc1) + (int)(py * sc1) * r1;
        const int i2 = (int)(px * sc2) + (int)(py * sc2) * r2;
        const int i3 = (int)(px * sc3) + (int)(py * sc3) * r3;

        float2 e2, e3;
        if (odd) {
            // LOD6, LOD7: L2-resident fp32 global gathers (issued back-to-back).
            e2 = __ldg(&cb6[i2]);
            e3 = __ldg(&cb7[i3]);
        } else {
            const float2 t2 = __half22float2(sh[o2 + i2]);
            const float2 t3 = __half22float2(sh[o3 + i3]);
            e2 = make_float2(t2.x * SD, t2.y * SD);
            e3 = make_float2(t3.x * SD, t3.y * SD);
        }
        const float2 v0 = __half22float2(sh[o0 + i0]);
        const float2 v1 = __half22float2(sh[o1 + i1]);

        float4 w;
        if (ycomp)
            w = make_float4(v0.y * SD, v1.y * SD, e2.y, e3.y);
        else
            w = make_float4(v0.x * SD, v1.x * SD, e2.x, e3.x);

        // Fully coalesced streaming store (output is write-once).
        __stcs(&out[(size_t)base * 4 + l], w);
    }
}

extern "C" void kernel_launch(void* const* d_in, const int* in_sizes, int n_in,
                              void* d_out, int out_size)
{
    const float2* pts = (const float2*)d_in[0];
    const float2* cb0 = (const float2*)d_in[1];
    const float2* cb1 = (const float2*)d_in[2];
    const float2* cb2 = (const float2*)d_in[3];
    const float2* cb3 = (const float2*)d_in[4];
    const float2* cb4 = (const float2*)d_in[5];
    const float2* cb5 = (const float2*)d_in[6];
    const float2* cb6 = (const float2*)d_in[7];
    const float2* cb7 = (const float2*)d_in[8];
    float4* out = (float4*)d_out;

    const int n = in_sizes[0] / 2;

    static int sm_count = -1;
    if (sm_count < 0) {
        cudaFuncSetAttribute(dense_grid_occ8_kernel,
                             cudaFuncAttributeMaxDynamicSharedMemorySize,
                             SMEM_BYTES);
        cudaDeviceGetAttribute(&sm_count, cudaDevAttrMultiProcessorCount, 0);
    }

    dense_grid_occ8_kernel<<<sm_count * 2, TPB, SMEM_BYTES>>>(
        pts, cb0, cb1, cb2, cb3, cb4, cb5, cb6, cb7, out, n);
}

// round 11
// speedup vs baseline: 1.0687x; 1.0687x over previous
#include <cuda_runtime.h>
#include <cuda_fp16.h>

// LODs = int(16*(256/16)^(L/7)) = 16,23,35,52,78,115,172,256
// entries: 256, 529, 1225, 2704, 6084, 13225, 29584, 65536
// LODs 0-6 in smem as scaled __half2 (53607*4B = 214.4KB); LOD7 in L2 (fp32).
//
// 8-point warp tile, chunk-per-lane (lane l = a*4+c handles chunk c of point
// base+a), no shuffles, one coalesced STG.128 per lane. One-deep software
// pipeline: next iteration's pts load and cb7 gather are issued during the
// current iteration so their latency is off the critical path.
//   chunk 0: x of LODs0-3   chunk 1: x of LODs4-7
//   chunk 2: y of LODs0-3   chunk 3: y of LODs4-7

#define SMEM_H2 53607
#define SMEM_BYTES (SMEM_H2 * 4)
#define SD (1.0f / 1024.0f)
#define SU 1024.0f
#define TPB 1024

__global__ void __launch_bounds__(TPB, 1)
dense_grid_pipe_kernel(const float2* __restrict__ pts,
                       const float2* __restrict__ cb0,
                       const float2* __restrict__ cb1,
                       const float2* __restrict__ cb2,
                       const float2* __restrict__ cb3,
                       const float2* __restrict__ cb4,
                       const float2* __restrict__ cb5,
                       const float2* __restrict__ cb6,
                       const float2* __restrict__ cb7,
                       float4* __restrict__ out,
                       int n)
{
    extern __shared__ __half2 sh[];

    // ---- Stage LODs 0-6 into smem as scaled half2 (coalesced) ----
    {
        const float2* __restrict__ srcs[7] = {cb0, cb1, cb2, cb3, cb4, cb5, cb6};
        const int cnt[7] = {256, 529, 1225, 2704, 6084, 13225, 29584};
        const int off[7] = {0, 256, 785, 2010, 4714, 10798, 24023};
#pragma unroll
        for (int L = 0; L < 7; ++L) {
            const float2* src = srcs[L];
            __half2* dst = sh + off[L];
            const int cn = cnt[L];
            for (int j = threadIdx.x; j < cn; j += TPB) {
                const float2 v = __ldg(&src[j]);
                dst[j] = __floats2half2_rn(v.x * SU, v.y * SU);
            }
        }
    }
    __syncthreads();

    const int l = threadIdx.x & 31;
    const int c = l & 3;
    const bool odd = (c & 1);        // odd chunk -> LODs 4-7
    const bool ycomp = (c & 2) != 0; // high chunk -> y component
    const int a = l >> 2;

    // Per-lane LOD-set constants (hoisted).
    const float sc0 = odd ? 77.0f : 15.0f;
    const float sc1 = odd ? 114.0f : 22.0f;
    const float sc2 = odd ? 171.0f : 34.0f;
    const float sc3 = odd ? 255.0f : 51.0f;
    const int r0 = odd ? 78 : 16;
    const int r1 = odd ? 115 : 23;
    const int r2 = odd ? 172 : 35;
    const int r3 = odd ? 256 : 52;
    const int o0 = odd ? 4714 : 0;
    const int o1 = odd ? 10798 : 256;
    const int o2 = odd ? 24023 : 785;
    const int o3 = 2010;             // LOD3 (even path); odd path uses cb7

    // Each warp owns 8 consecutive points per iteration (n % 8 == 0).
    const int base0 = ((blockIdx.x * TPB + (threadIdx.x & ~31)) >> 2);
    const int stride = (gridDim.x * TPB) >> 2;   // points per sweep

    // ---- Pipeline prologue: load point + issue cb7 gather for iter 0 ----
    float2 p = make_float2(0.f, 0.f);
    float2 g7 = make_float2(0.f, 0.f);
    if (base0 < n) {
        p = __ldg(&pts[base0 + a]);
        if (odd) {
            const int i3 = (int)(p.x * sc3) + (int)(p.y * sc3) * r3;
            g7 = __ldg(&cb7[i3]);
        }
    }

    for (int base = base0; base < n; base += stride) {
        const int nbase = base + stride;

        // ---- Issue next iteration's loads first (latency hiding) ----
        float2 pn = p, g7n = g7;
        if (nbase < n) {
            pn = __ldg(&pts[nbase + a]);
            if (odd) {
                const int i3n = (int)(pn.x * sc3) + (int)(pn.y * sc3) * r3;
                g7n = __ldg(&cb7[i3n]);
            }
        }

        // ---- Current iteration (p, g7 already resident) ----
        const float px = p.x, py = p.y;
        // trunc == floor for nonneg; same single fp32 multiply as reference
        const int i0 = (int)(px * sc0) + (int)(py * sc0) * r0;
        const int i1 = (int)(px * sc1) + (int)(py * sc1) * r1;
        const int i2 = (int)(px * sc2) + (int)(py * sc2) * r2;

        float2 g;
        if (odd) {
            g = g7;
        } else {
            const int i3 = (int)(px * sc3) + (int)(py * sc3) * r3;
            const float2 t = __half22float2(sh[o3 + i3]);
            g = make_float2(t.x * SD, t.y * SD);
        }

        const float2 v0 = __half22float2(sh[o0 + i0]);
        const float2 v1 = __half22float2(sh[o1 + i1]);
        const float2 v2 = __half22float2(sh[o2 + i2]);

        float4 w;
        if (ycomp)
            w = make_float4(v0.y * SD, v1.y * SD, v2.y * SD, g.y);
        else
            w = make_float4(v0.x * SD, v1.x * SD, v2.x * SD, g.x);

        // Fully coalesced streaming store (output is write-once).
        __stcs(&out[(size_t)base * 4 + l], w);

        p = pn;
        g7 = g7n;
    }
}

extern "C" void kernel_launch(void* const* d_in, const int* in_sizes, int n_in,
                              void* d_out, int out_size)
{
    const float2* pts = (const float2*)d_in[0];
    const float2* cb0 = (const float2*)d_in[1];
    const float2* cb1 = (const float2*)d_in[2];
    const float2* cb2 = (const float2*)d_in[3];
    const float2* cb3 = (const float2*)d_in[4];
    const float2* cb4 = (const float2*)d_in[5];
    const float2* cb5 = (const float2*)d_in[6];
    const float2* cb6 = (const float2*)d_in[7];
    const float2* cb7 = (const float2*)d_in[8];
    float4* out = (float4*)d_out;

    const int n = in_sizes[0] / 2;

    static int sm_count = -1;
    if (sm_count < 0) {
        cudaFuncSetAttribute(dense_grid_pipe_kernel,
                             cudaFuncAttributeMaxDynamicSharedMemorySize,
                             SMEM_BYTES);
        cudaDeviceGetAttribute(&sm_count, cudaDevAttrMultiProcessorCount, 0);
    }

    dense_grid_pipe_kernel<<<sm_count, TPB, SMEM_BYTES>>>(
        pts, cb0, cb1, cb2, cb3, cb4, cb5, cb6, cb7, out, n);
}

// round 12
// speedup vs baseline: 1.2124x; 1.1344x over previous
#include <cuda_runtime.h>
#include <cuda_fp16.h>

// LODs = int(16*(256/16)^(L/7)) = 16,23,35,52,78,115,172,256
// entries: 256, 529, 1225, 2704, 6084, 13225, 29584, 65536
// LODs 0-6 in smem as scaled __half2 (53607*4B = 214.4KB); LOD7 in L2 (fp32).
//
// 8-point warp tile, chunk-per-lane (lane l = a*4+c handles chunk c of point
// base+a), no shuffles, one coalesced STG.128 per lane. Branch-free pts
// prefetch: next iteration's point is loaded with a clamped index at the top
// of each iteration, removing the DRAM pts latency from the dependence chain.
//   chunk 0: x of LODs0-3   chunk 1: x of LODs4-7
//   chunk 2: y of LODs0-3   chunk 3: y of LODs4-7

#define SMEM_H2 53607
#define SMEM_BYTES (SMEM_H2 * 4)
#define SD (1.0f / 1024.0f)
#define SU 1024.0f
#define TPB 1024

__global__ void __launch_bounds__(TPB, 1)
dense_grid_pf_kernel(const float2* __restrict__ pts,
                     const float2* __restrict__ cb0,
                     const float2* __restrict__ cb1,
                     const float2* __restrict__ cb2,
                     const float2* __restrict__ cb3,
                     const float2* __restrict__ cb4,
                     const float2* __restrict__ cb5,
                     const float2* __restrict__ cb6,
                     const float2* __restrict__ cb7,
                     float4* __restrict__ out,
                     int n)
{
    extern __shared__ __half2 sh[];

    // ---- Stage LODs 0-6 into smem as scaled half2 (coalesced) ----
    {
        const float2* __restrict__ srcs[7] = {cb0, cb1, cb2, cb3, cb4, cb5, cb6};
        const int cnt[7] = {256, 529, 1225, 2704, 6084, 13225, 29584};
        const int off[7] = {0, 256, 785, 2010, 4714, 10798, 24023};
#pragma unroll
        for (int L = 0; L < 7; ++L) {
            const float2* src = srcs[L];
            __half2* dst = sh + off[L];
            const int cn = cnt[L];
            for (int j = threadIdx.x; j < cn; j += TPB) {
                const float2 v = __ldg(&src[j]);
                dst[j] = __floats2half2_rn(v.x * SU, v.y * SU);
            }
        }
    }
    __syncthreads();

    const int l = threadIdx.x & 31;
    const int c = l & 3;
    const bool odd = (c & 1);        // odd chunk -> LODs 4-7
    const bool ycomp = (c & 2) != 0; // high chunk -> y component
    const int a = l >> 2;

    // Per-lane LOD-set constants (hoisted).
    const float sc0 = odd ? 77.0f : 15.0f;
    const float sc1 = odd ? 114.0f : 22.0f;
    const float sc2 = odd ? 171.0f : 34.0f;
    const float sc3 = odd ? 255.0f : 51.0f;
    const int r0 = odd ? 78 : 16;
    const int r1 = odd ? 115 : 23;
    const int r2 = odd ? 172 : 35;
    const int r3 = odd ? 256 : 52;
    const int o0 = odd ? 4714 : 0;
    const int o1 = odd ? 10798 : 256;
    const int o2 = odd ? 24023 : 785;
    const int o3 = 2010;             // LOD3 (even path); odd path uses cb7

    // Each warp owns 8 consecutive points per iteration (n % 8 == 0).
    const int base0 = ((blockIdx.x * TPB + (threadIdx.x & ~31)) >> 2);
    const int stride = (gridDim.x * TPB) >> 2;   // points per sweep

    if (base0 >= n) return;

    // Prologue: point for the first iteration.
    float2 p = __ldg(&pts[base0 + a]);

    for (int base = base0; base < n; base += stride) {
        // ---- Branch-free prefetch of next iteration's point ----
        const int nidx = min(base + stride + a, n - 1);
        const float2 pn = __ldg(&pts[nidx]);

        // ---- Current iteration (p already resident) ----
        const float px = p.x, py = p.y;
        // trunc == floor for nonneg; same single fp32 multiply as reference
        const int i0 = (int)(px * sc0) + (int)(py * sc0) * r0;
        const int i1 = (int)(px * sc1) + (int)(py * sc1) * r1;
        const int i2 = (int)(px * sc2) + (int)(py * sc2) * r2;
        const int i3 = (int)(px * sc3) + (int)(py * sc3) * r3;

        // Last element: LOD7 (global fp32, L2-resident) for odd chunks.
        float2 g;
        if (odd) {
            g = __ldg(&cb7[i3]);
        } else {
            const float2 t = __half22float2(sh[o3 + i3]);
            g = make_float2(t.x * SD, t.y * SD);
        }

        const float2 v0 = __half22float2(sh[o0 + i0]);
        const float2 v1 = __half22float2(sh[o1 + i1]);
        const float2 v2 = __half22float2(sh[o2 + i2]);

        float4 w;
        if (ycomp)
            w = make_float4(v0.y * SD, v1.y * SD, v2.y * SD, g.y);
        else
            w = make_float4(v0.x * SD, v1.x * SD, v2.x * SD, g.x);

        // Fully coalesced streaming store (output is write-once).
        __stcs(&out[(size_t)base * 4 + l], w);

        p = pn;
    }
}

extern "C" void kernel_launch(void* const* d_in, const int* in_sizes, int n_in,
                              void* d_out, int out_size)
{
    const float2* pts = (const float2*)d_in[0];
    const float2* cb0 = (const float2*)d_in[1];
    const float2* cb1 = (const float2*)d_in[2];
    const float2* cb2 = (const float2*)d_in[3];
    const float2* cb3 = (const float2*)d_in[4];
    const float2* cb4 = (const float2*)d_in[5];
    const float2* cb5 = (const float2*)d_in[6];
    const float2* cb6 = (const float2*)d_in[7];
    const float2* cb7 = (const float2*)d_in[8];
    float4* out = (float4*)d_out;

    const int n = in_sizes[0] / 2;

    static int sm_count = -1;
    if (sm_count < 0) {
        cudaFuncSetAttribute(dense_grid_pf_kernel,
                             cudaFuncAttributeMaxDynamicSharedMemorySize,
                             SMEM_BYTES);
        cudaDeviceGetAttribute(&sm_count, cudaDevAttrMultiProcessorCount, 0);
    }

    dense_grid_pf_kernel<<<sm_count, TPB, SMEM_BYTES>>>(
        pts, cb0, cb1, cb2, cb3, cb4, cb5, cb6, cb7, out, n);
}

// round 13
// speedup vs baseline: 1.2131x; 1.0006x over previous
#include <cuda_runtime.h>
#include <cuda_fp16.h>

// LODs = int(16*(256/16)^(L/7)) = 16,23,35,52,78,115,172,256
// entries: 256, 529, 1225, 2704, 6084, 13225, 29584, 65536
// LODs 0-6 in smem as scaled __half2 (53607*4B = 214.4KB); LOD7 in L2 (fp32).
//
// 8-point warp tile, chunk-per-lane (lane l = a*4+c handles chunk c of point
// base+a), no shuffles, one coalesced STG.128 per lane.
// Two-deep branch-free pipeline: points are prefetched 2 sweeps ahead
// (clamped index), and each iteration issues the cb7 gather for the NEXT
// sweep from the already-resident next point. Every consumed value was
// loaded a full iteration earlier -> no exposed load latency in the chain.
//   chunk 0: x of LODs0-3   chunk 1: x of LODs4-7
//   chunk 2: y of LODs0-3   chunk 3: y of LODs4-7

#define SMEM_H2 53607
#define SMEM_BYTES (SMEM_H2 * 4)
#define SD (1.0f / 1024.0f)
#define SU 1024.0f
#define TPB 1024

__global__ void __launch_bounds__(TPB, 1)
dense_grid_pf2_kernel(const float2* __restrict__ pts,
                      const float2* __restrict__ cb0,
                      const float2* __restrict__ cb1,
                      const float2* __restrict__ cb2,
                      const float2* __restrict__ cb3,
                      const float2* __restrict__ cb4,
                      const float2* __restrict__ cb5,
                      const float2* __restrict__ cb6,
                      const float2* __restrict__ cb7,
                      float4* __restrict__ out,
                      int n)
{
    extern __shared__ __half2 sh[];

    // ---- Stage LODs 0-6 into smem as scaled half2 (coalesced) ----
    {
        const float2* __restrict__ srcs[7] = {cb0, cb1, cb2, cb3, cb4, cb5, cb6};
        const int cnt[7] = {256, 529, 1225, 2704, 6084, 13225, 29584};
        const int off[7] = {0, 256, 785, 2010, 4714, 10798, 24023};
#pragma unroll
        for (int L = 0; L < 7; ++L) {
            const float2* src = srcs[L];
            __half2* dst = sh + off[L];
            const int cn = cnt[L];
            for (int j = threadIdx.x; j < cn; j += TPB) {
                const float2 v = __ldg(&src[j]);
                dst[j] = __floats2half2_rn(v.x * SU, v.y * SU);
            }
        }
    }
    __syncthreads();

    const int l = threadIdx.x & 31;
    const int c = l & 3;
    const bool odd = (c & 1);        // odd chunk -> LODs 4-7
    const bool ycomp = (c & 2) != 0; // high chunk -> y component
    const int a = l >> 2;

    // Per-lane LOD-set constants (hoisted).
    const float sc0 = odd ? 77.0f : 15.0f;
    const float sc1 = odd ? 114.0f : 22.0f;
    const float sc2 = odd ? 171.0f : 34.0f;
    const float sc3 = odd ? 255.0f : 51.0f;
    const int r0 = odd ? 78 : 16;
    const int r1 = odd ? 115 : 23;
    const int r2 = odd ? 172 : 35;
    const int r3 = odd ? 256 : 52;
    const int o0 = odd ? 4714 : 0;
    const int o1 = odd ? 10798 : 256;
    const int o2 = odd ? 24023 : 785;
    const int o3 = 2010;             // LOD3 (even path); odd path uses cb7

    // Each warp owns 8 consecutive points per iteration (n % 8 == 0).
    const int base0 = ((blockIdx.x * TPB + (threadIdx.x & ~31)) >> 2);
    const int stride = (gridDim.x * TPB) >> 2;   // points per sweep

    if (base0 >= n) return;

    // ---- Prologue: fill the 2-deep pipeline (clamped, branch-free) ----
    float2 p  = __ldg(&pts[base0 + a]);
    float2 p1 = __ldg(&pts[min(base0 + stride + a, n - 1)]);
    float2 g7 = make_float2(0.f, 0.f);
    if (odd) {
        const int i3 = (int)(p.x * sc3) + (int)(p.y * sc3) * r3;
        g7 = __ldg(&cb7[i3]);
    }

    for (int base = base0; base < n; base += stride) {
        // ---- Prefetch point 2 sweeps ahead (branch-free) ----
        const float2 pp = __ldg(&pts[min(base + 2 * stride + a, n - 1)]);

        // ---- Issue next sweep's cb7 gather from resident p1 ----
        float2 g7n = make_float2(0.f, 0.f);
        if (odd) {
            const int i3n = (int)(p1.x * sc3) + (int)(p1.y * sc3) * r3;
            g7n = __ldg(&cb7[i3n]);
        }

        // ---- Current iteration (p, g7 resident) ----
        const float px = p.x, py = p.y;
        // trunc == floor for nonneg; same single fp32 multiply as reference
        const int i0 = (int)(px * sc0) + (int)(py * sc0) * r0;
        const int i1 = (int)(px * sc1) + (int)(py * sc1) * r1;
        const int i2 = (int)(px * sc2) + (int)(py * sc2) * r2;

        float2 g;
        if (odd) {
            g = g7;
        } else {
            const int i3 = (int)(px * sc3) + (int)(py * sc3) * r3;
            const float2 t = __half22float2(sh[o3 + i3]);
            g = make_float2(t.x * SD, t.y * SD);
        }

        const float2 v0 = __half22float2(sh[o0 + i0]);
        const float2 v1 = __half22float2(sh[o1 + i1]);
        const float2 v2 = __half22float2(sh[o2 + i2]);

        float4 w;
        if (ycomp)
            w = make_float4(v0.y * SD, v1.y * SD, v2.y * SD, g.y);
        else
            w = make_float4(v0.x * SD, v1.x * SD, v2.x * SD, g.x);

        // Fully coalesced streaming store (output is write-once).
        __stcs(&out[(size_t)base * 4 + l], w);

        // ---- Rotate the pipeline ----
        p = p1;
        p1 = pp;
        g7 = g7n;
    }
}

extern "C" void kernel_launch(void* const* d_in, const int* in_sizes, int n_in,
                              void* d_out, int out_size)
{
    const float2* pts = (const float2*)d_in[0];
    const float2* cb0 = (const float2*)d_in[1];
    const float2* cb1 = (const float2*)d_in[2];
    const float2* cb2 = (const float2*)d_in[3];
    const float2* cb3 = (const float2*)d_in[4];
    const float2* cb4 = (const float2*)d_in[5];
    const float2* cb5 = (const float2*)d_in[6];
    const float2* cb6 = (const float2*)d_in[7];
    const float2* cb7 = (const float2*)d_in[8];
    float4* out = (float4*)d_out;

    const int n = in_sizes[0] / 2;

    static int sm_count = -1;
    if (sm_count < 0) {
        cudaFuncSetAttribute(dense_grid_pf2_kernel,
                             cudaFuncAttributeMaxDynamicSharedMemorySize,
                             SMEM_BYTES);
        cudaDeviceGetAttribute(&sm_count, cudaDevAttrMultiProcessorCount, 0);
    }

    dense_grid_pf2_kernel<<<sm_count, TPB, SMEM_BYTES>>>(
        pts, cb0, cb1, cb2, cb3, cb4, cb5, cb6, cb7, out, n);
}